// round 1
// baseline (speedup 1.0000x reference)
#include <cuda_runtime.h>

// Problem constants
#define Bn 8
#define Nn 1024
#define Dn 512
#define Hn 8
#define DHn 64
#define BHn (Bn*Hn)          // 64
#define SCALE 0.125f         // 1/sqrt(64)

// Scratch (allocation-free rule: __device__ globals)
__device__ float g_q[BHn*Nn*DHn];          // [bh, n, dh]
__device__ float g_k[BHn*Nn*DHn];
__device__ float g_v[BHn*Nn*DHn];
__device__ float g_attn[BHn*Nn*Nn];        // 268 MB
__device__ float g_otmp[Bn*Nn*Dn];         // concat heads [b, n, h*dh]

// ---------------------------------------------------------------------------
// Generic NT GEMM: C[m, o] = sum_k A[m,k] * W[o,k]   (M=8192, Nout=512, K=512)
// MODE 0/1/2: A = x, write to g_q/g_k/g_v in [bh, n, dh] layout
// MODE 3:     A = g_otmp, write Cout[m*512+o] + bias[o]
// ---------------------------------------------------------------------------
template<int MODE>
__global__ __launch_bounds__(256) void gemm_nt(const float* __restrict__ A,
                                               const float* __restrict__ Wm,
                                               const float* __restrict__ bias,
                                               float* __restrict__ Cout)
{
    __shared__ float As[16][65];   // [k][m]
    __shared__ float Bs[16][65];   // [k][o]
    const int m0 = blockIdx.y * 64;
    const int n0 = blockIdx.x * 64;
    const int tid = threadIdx.x;
    const int tx = tid & 15, ty = tid >> 4;

    const float* Asrc = (MODE == 3) ? (const float*)g_otmp : A;

    float acc[4][4];
#pragma unroll
    for (int i = 0; i < 4; i++)
#pragma unroll
        for (int j = 0; j < 4; j++) acc[i][j] = 0.f;

    const int row = tid >> 2;        // 0..63
    const int kk  = (tid & 3) * 4;   // 0,4,8,12

    for (int k0 = 0; k0 < Dn; k0 += 16) {
        float4 va = *(const float4*)(Asrc + (size_t)(m0 + row) * Dn + k0 + kk);
        float4 vb = *(const float4*)(Wm   + (size_t)(n0 + row) * Dn + k0 + kk);
        As[kk+0][row] = va.x; As[kk+1][row] = va.y; As[kk+2][row] = va.z; As[kk+3][row] = va.w;
        Bs[kk+0][row] = vb.x; Bs[kk+1][row] = vb.y; Bs[kk+2][row] = vb.z; Bs[kk+3][row] = vb.w;
        __syncthreads();
#pragma unroll
        for (int k = 0; k < 16; k++) {
            float a[4], b[4];
#pragma unroll
            for (int i = 0; i < 4; i++) a[i] = As[k][ty*4 + i];
#pragma unroll
            for (int j = 0; j < 4; j++) b[j] = Bs[k][tx*4 + j];
#pragma unroll
            for (int i = 0; i < 4; i++)
#pragma unroll
                for (int j = 0; j < 4; j++)
                    acc[i][j] = fmaf(a[i], b[j], acc[i][j]);
        }
        __syncthreads();
    }

    float* Cq = (MODE == 0) ? g_q : (MODE == 1) ? g_k : (MODE == 2) ? g_v : Cout;

#pragma unroll
    for (int i = 0; i < 4; i++) {
#pragma unroll
        for (int j = 0; j < 4; j++) {
            const int m = m0 + ty*4 + i;
            const int o = n0 + tx*4 + j;
            if (MODE <= 2) {
                const int bb = m >> 10, nn = m & (Nn - 1);
                const int hh = o >> 6,  dd = o & 63;
                Cq[(size_t)(((bb << 3) | hh) << 16) + (nn << 6) + dd] = acc[i][j];
            } else {
                Cq[(size_t)m * Dn + o] = acc[i][j] + bias[o];
            }
        }
    }
}

// ---------------------------------------------------------------------------
// Fused QK^T + relative bias:  attn[bh,i,j] = (Q_i . (K_j + E[j-i+1023])) * SCALE
// Tiles: 64x64 of (i,j); E window = 127 rows in smem.
// ---------------------------------------------------------------------------
__global__ __launch_bounds__(256) void qk_rel(const float* __restrict__ E)
{
    __shared__ float Qs[32][64];     // [d][i]  (half of dh at a time)
    __shared__ float Ks[32][64];     // [d][j]
    __shared__ float Es[64][127];    // [d][r],  r = l - l0

    const int bh = blockIdx.z;
    const int i0 = blockIdx.y * 64;
    const int j0 = blockIdx.x * 64;
    const int l0 = j0 - i0 + (Nn - 64);   // j0-i0+960; window [l0, l0+126] always valid
    const int tid = threadIdx.x;

    // load E window (127 x 64)
    for (int e = tid; e < 127 * 64; e += 256) {
        const int r = e >> 6, d = e & 63;
        Es[d][r] = E[(size_t)(l0 + r) * 64 + d];
    }

    const int tx = tid & 15, ty = tid >> 4;
    const int ib = ty * 4, jb = tx * 4;
    float acc[4][4];
#pragma unroll
    for (int i = 0; i < 4; i++)
#pragma unroll
        for (int j = 0; j < 4; j++) acc[i][j] = 0.f;

    const float* qbase = g_q + ((size_t)bh * Nn + i0) * DHn;
    const float* kbase = g_k + ((size_t)bh * Nn + j0) * DHn;
    const int r    = tid >> 2;        // 0..63
    const int dblk = (tid & 3) * 8;   // 0,8,16,24

#pragma unroll
    for (int half = 0; half < 2; half++) {
        __syncthreads();   // E visible (1st iter) / previous compute done (2nd iter)
#pragma unroll
        for (int u = 0; u < 8; u += 4) {
            float4 vq = *(const float4*)(qbase + (size_t)r * 64 + half*32 + dblk + u);
            float4 vk = *(const float4*)(kbase + (size_t)r * 64 + half*32 + dblk + u);
            Qs[dblk+u+0][r] = vq.x; Qs[dblk+u+1][r] = vq.y;
            Qs[dblk+u+2][r] = vq.z; Qs[dblk+u+3][r] = vq.w;
            Ks[dblk+u+0][r] = vk.x; Ks[dblk+u+1][r] = vk.y;
            Ks[dblk+u+2][r] = vk.z; Ks[dblk+u+3][r] = vk.w;
        }
        __syncthreads();
#pragma unroll
        for (int d = 0; d < 32; d++) {
            const int dg = half * 32 + d;
            float a[4], b[4];
#pragma unroll
            for (int i = 0; i < 4; i++) a[i] = Qs[d][ib + i];
#pragma unroll
            for (int j = 0; j < 4; j++) b[j] = Ks[d][jb + j];
#pragma unroll
            for (int i = 0; i < 4; i++)
#pragma unroll
                for (int j = 0; j < 4; j++)
                    acc[i][j] = fmaf(a[i], b[j] + Es[dg][jb + j - ib - i + 63], acc[i][j]);
        }
    }

    float* dst = g_attn + ((size_t)bh * Nn + i0) * Nn + j0;
#pragma unroll
    for (int i = 0; i < 4; i++)
#pragma unroll
        for (int j = 0; j < 4; j++)
            dst[(size_t)(ib + i) * Nn + jb + j] = acc[i][j] * SCALE;
}

// ---------------------------------------------------------------------------
// Row softmax over last dim (length 1024). One block per row, 256 threads.
// ---------------------------------------------------------------------------
__global__ __launch_bounds__(256) void softmax_rows()
{
    float* p = g_attn + (size_t)blockIdx.x * Nn;
    const int tid = threadIdx.x;
    float v0 = p[tid], v1 = p[tid + 256], v2 = p[tid + 512], v3 = p[tid + 768];

    float m = fmaxf(fmaxf(v0, v1), fmaxf(v2, v3));
#pragma unroll
    for (int o = 16; o; o >>= 1) m = fmaxf(m, __shfl_xor_sync(0xffffffffu, m, o));
    __shared__ float red[8];
    if ((tid & 31) == 0) red[tid >> 5] = m;
    __syncthreads();
    m = red[0];
#pragma unroll
    for (int w = 1; w < 8; w++) m = fmaxf(m, red[w]);

    v0 = __expf(v0 - m); v1 = __expf(v1 - m);
    v2 = __expf(v2 - m); v3 = __expf(v3 - m);
    float s = v0 + v1 + v2 + v3;
#pragma unroll
    for (int o = 16; o; o >>= 1) s += __shfl_xor_sync(0xffffffffu, s, o);
    __syncthreads();
    if ((tid & 31) == 0) red[tid >> 5] = s;
    __syncthreads();
    s = 0.f;
#pragma unroll
    for (int w = 0; w < 8; w++) s += red[w];

    const float inv = 1.0f / s;
    p[tid]       = v0 * inv;
    p[tid + 256] = v1 * inv;
    p[tid + 512] = v2 * inv;
    p[tid + 768] = v3 * inv;
}

// ---------------------------------------------------------------------------
// out[bh,i,d] = (sum_j P[i,j] * V[j,d]) * phase[bh,i]; write concat-head layout
// ---------------------------------------------------------------------------
__global__ __launch_bounds__(256) void av_phase(const float* __restrict__ phase)
{
    __shared__ float Ps[32][65];   // [j][i]
    __shared__ float Vs[32][64];   // [j][d]
    const int bh = blockIdx.y;
    const int i0 = blockIdx.x * 64;
    const int tid = threadIdx.x;
    const int tx = tid & 15, ty = tid >> 4;

    float acc[4][4];
#pragma unroll
    for (int i = 0; i < 4; i++)
#pragma unroll
        for (int j = 0; j < 4; j++) acc[i][j] = 0.f;

    const float* prow  = g_attn + ((size_t)bh * Nn + i0) * Nn;
    const float* vbase = g_v + (size_t)bh * Nn * DHn;
    const int ri = tid >> 2;        // 0..63 (i)
    const int jq = (tid & 3) * 8;   // 0..24 (j chunk)
    const int rv = tid >> 3;        // 0..31 (j for V)
    const int dq = (tid & 7) * 8;   // 0..56 (d chunk)

    for (int k0 = 0; k0 < Nn; k0 += 32) {
#pragma unroll
        for (int u = 0; u < 8; u += 4) {
            float4 vp = *(const float4*)(prow + (size_t)ri * Nn + k0 + jq + u);
            Ps[jq+u+0][ri] = vp.x; Ps[jq+u+1][ri] = vp.y;
            Ps[jq+u+2][ri] = vp.z; Ps[jq+u+3][ri] = vp.w;
        }
#pragma unroll
        for (int u = 0; u < 8; u += 4) {
            float4 vv = *(const float4*)(vbase + (size_t)(k0 + rv) * DHn + dq + u);
            Vs[rv][dq+u+0] = vv.x; Vs[rv][dq+u+1] = vv.y;
            Vs[rv][dq+u+2] = vv.z; Vs[rv][dq+u+3] = vv.w;
        }
        __syncthreads();
#pragma unroll
        for (int k = 0; k < 32; k++) {
            float a[4], b[4];
#pragma unroll
            for (int i = 0; i < 4; i++) a[i] = Ps[k][ty*4 + i];
#pragma unroll
            for (int j = 0; j < 4; j++) b[j] = Vs[k][tx*4 + j];
#pragma unroll
            for (int i = 0; i < 4; i++)
#pragma unroll
                for (int j = 0; j < 4; j++)
                    acc[i][j] = fmaf(a[i], b[j], acc[i][j]);
        }
        __syncthreads();
    }

    const int bb = bh >> 3, hh = bh & 7;
#pragma unroll
    for (int i = 0; i < 4; i++) {
        const int gi = i0 + ty*4 + i;
        const float ph = phase[(size_t)bh * Nn + gi];
#pragma unroll
        for (int j = 0; j < 4; j++) {
            const int dd = tx*4 + j;
            g_otmp[(size_t)(bb * Nn + gi) * Dn + hh*64 + dd] = acc[i][j] * ph;
        }
    }
}

// ---------------------------------------------------------------------------
extern "C" void kernel_launch(void* const* d_in, const int* in_sizes, int n_in,
                              void* d_out, int out_size)
{
    const float* x     = (const float*)d_in[0];
    const float* phase = (const float*)d_in[1];
    const float* E     = (const float*)d_in[2];
    const float* Wq    = (const float*)d_in[3];
    const float* Wk    = (const float*)d_in[4];
    const float* Wv    = (const float*)d_in[5];
    const float* Wo    = (const float*)d_in[6];
    const float* bo    = (const float*)d_in[7];
    float* out = (float*)d_out;

    dim3 gproj(Dn / 64, (Bn * Nn) / 64);   // (8, 128)

    gemm_nt<0><<<gproj, 256>>>(x, Wq, nullptr, nullptr);
    gemm_nt<1><<<gproj, 256>>>(x, Wk, nullptr, nullptr);
    gemm_nt<2><<<gproj, 256>>>(x, Wv, nullptr, nullptr);

    qk_rel<<<dim3(Nn / 64, Nn / 64, BHn), 256>>>(E);

    softmax_rows<<<BHn * Nn, 256>>>();

    av_phase<<<dim3(Nn / 64, BHn), 256>>>(phase);

    gemm_nt<3><<<gproj, 256>>>(nullptr, Wo, bo, out);
}